// round 11
// baseline (speedup 1.0000x reference)
#include <cuda_runtime.h>
#include <math.h>

#define NUM_CLASSES 10
#define Hh 480
#define Ww 640
#define SKIP 8
#define GY 60
#define GX 80
#define P  4800
#define NMAX 8
#define EPSF 1e-6f
#define INLIER 0.9f
#define VTILE 512
#define CBLK  128                        // candidates per vote block (1 per thread-lane)
#define NSLICE 4
#define VTHREADS (CBLK * NSLICE)         // 512
#define VOTE_BX ((P + CBLK - 1) / CBLK)  // 38
#define KD (NUM_CLASSES - 1)

// ---------------- device scratch ----------------
static __device__ float4   g_sxyuv[NMAX][P];      // class-sorted (x,y,u,v)
static __device__ float    g_sd[NMAX][P];         // class-sorted d
static __device__ int      g_segStart[NMAX][11];
static __device__ float    g_counts[NMAX][10];
static __device__ unsigned g_bestkey[NMAX][10];   // (cnt<<13)|(8191-c)

// shared inlier predicate: fast quadratic test + exact IEEE fallback in guard band.
// Used identically by vote and final so inlier sets match exactly.
__device__ __forceinline__ bool hv_inlier(float fcx, float fcy, float4 t)
{
    float dx   = fcx - t.x;
    float dy   = fcy - t.y;
    float s    = fmaf(dx, dx, dy * dy);
    float dot  = fmaf(t.z, dx, t.w * dy);
    float dotp = fmaxf(dot, 0.0f);
    float gd   = fmaf(dotp, dotp, -0.81f * s);
    if (fabsf(gd) < 1e-5f * s) {
        float rd = sqrtf(s) + EPSF;              // exact reference formula
        return (dot / rd) > INLIER;
    }
    return gd > 0.0f;
}

// ================= K1: sort + fused gather + output zeroing (1 block/n, 1024 thr) =================
__global__ void __launch_bounds__(1024, 1)
hv_prep_kernel(const int* __restrict__ label,
               const float* __restrict__ vp,
               float* __restrict__ out, int N)
{
    const int n    = blockIdx.x;
    const int tid  = threadIdx.x;
    const int warp = tid >> 5;
    const int lane = tid & 31;
    const unsigned FULL = 0xffffffffu;

    __shared__ int   s_lab[P];
    __shared__ short s_sidx[P];     // sorted pos -> pixel index
    __shared__ int   s_cnt[32][10];
    __shared__ int   s_off[32][10];

    if (tid < 10) g_bestkey[n][tid] = 0u;
    {   // zero train-only output slices for this n
        float* targ = out + (size_t)N * KD * 14 + (size_t)n * KD * 40;
        float* wgt  = out + (size_t)N * KD * 54 + (size_t)n * KD * 40;
        for (int i = tid; i < KD * 40; i += 1024) { targ[i] = 0.0f; wgt[i] = 0.0f; }
    }

    // stage labels
    const int* lab2d = label + (size_t)n * Hh * Ww;
    for (int p = tid; p < P; p += 1024) {
        int iy = p / GX, ix = p - iy * GX;
        s_lab[p] = lab2d[iy * SKIP * Ww + ix * SKIP];
    }
    __syncthreads();

    // per-chunk per-class counts (warp = chunk of 150 pixels)
    int cnt[10];
    #pragma unroll
    for (int k = 0; k < 10; k++) cnt[k] = 0;
    const int cbase = warp * 150;
    #pragma unroll
    for (int s = 0; s < 5; s++) {
        int o = s * 32 + lane;
        int l = (o < 150) ? s_lab[cbase + o] : -1;
        #pragma unroll
        for (int k = 0; k < 10; k++) {
            unsigned m = __ballot_sync(FULL, l == k);
            cnt[k] += __popc(m);
        }
    }
    if (lane == 0) {
        #pragma unroll
        for (int k = 0; k < 10; k++) s_cnt[warp][k] = cnt[k];
    }
    __syncthreads();

    // warp 0: shfl-scan chunk offsets + segment starts
    if (warp == 0) {
        int segrun = 0;
        if (lane == 0) g_segStart[n][0] = 0;
        #pragma unroll
        for (int k = 0; k < 10; k++) {
            int v = s_cnt[lane][k];
            int incl = v;
            #pragma unroll
            for (int d = 1; d < 32; d <<= 1) {
                int t = __shfl_up_sync(FULL, incl, d);
                if (lane >= d) incl += t;
            }
            int excl  = incl - v;
            int total = __shfl_sync(FULL, incl, 31);
            if (k >= 1) {
                s_off[lane][k] = segrun + excl;
                if (lane == 0) g_segStart[n][k] = segrun;
                segrun += total;
            }
            if (lane == 0) g_counts[n][k] = (float)total;
        }
        if (lane == 0) g_segStart[n][10] = segrun;
    }
    __syncthreads();

    // parallel stable scatter of indices into smem (warp = chunk)
    int off[10];
    #pragma unroll
    for (int k = 1; k < 10; k++) off[k] = s_off[warp][k];
    #pragma unroll
    for (int s = 0; s < 5; s++) {
        int o = s * 32 + lane;
        int j = cbase + o;
        int l = (o < 150) ? s_lab[j] : -1;
        #pragma unroll
        for (int k = 1; k < 10; k++) {
            unsigned m = __ballot_sync(FULL, l == k);
            if (l == k) {
                int pos = off[k] + __popc(m & ((1u << lane) - 1u));
                s_sidx[pos] = (short)j;
            }
            off[k] += __popc(m);
        }
    }
    __syncthreads();

    // fused gather: compute (x,y,u,v,d) into sorted order (high MLP)
    const int total = g_segStart[n][10];
    const float* vpn = vp + (size_t)n * Hh * Ww * (3 * NUM_CLASSES);
    for (int pos = tid; pos < total; pos += 1024) {
        int p = (int)s_sidx[pos];
        int l = s_lab[p];
        int iy = p / GX, ix = p - iy * GX;
        const float* v3 = vpn + (size_t)(iy * SKIP * Ww + ix * SKIP) * (3 * NUM_CLASSES) + 3 * l;
        float u = v3[0], v = v3[1], w = v3[2];
        float nrm = sqrtf(u * u + v * v) + EPSF;
        g_sxyuv[n][pos] = make_float4((float)(ix * SKIP), (float)(iy * SKIP), u / nrm, v / nrm);
        g_sd[n][pos]    = expf(fminf(fmaxf(w, -3.0f), 3.0f));
    }
}

// ================= K2: voting (counts only) + fused argmax, 512 thr =================
__global__ void __launch_bounds__(VTHREADS)
hv_vote_kernel()
{
    const int n = blockIdx.z;
    const int k = blockIdx.y + 1;
    const int tid   = threadIdx.x;
    const int cl    = tid & (CBLK - 1);          // candidate lane 0..127
    const int slice = tid >> 7;                  // 0..3
    const int c     = blockIdx.x * CBLK + cl;

    __shared__ float4   sxy[VTILE];
    __shared__ int      s_pcnt[NSLICE][CBLK];
    __shared__ unsigned skey[CBLK];

    const int beg = g_segStart[n][k];
    const int end = g_segStart[n][k + 1];

    float fcx = 0.f, fcy = 0.f;
    const bool cv = (c < P);
    if (cv) {
        int iy = c / GX, ix = c - iy * GX;
        fcx = (float)(ix * SKIP);
        fcy = (float)(iy * SKIP);
    }

    int cnt = 0;

    for (int base = beg; base < end; base += VTILE) {
        int m = end - base;
        if (m > VTILE) m = VTILE;
        for (int j = tid; j < m; j += VTHREADS)
            sxy[j] = g_sxyuv[n][base + j];
        __syncthreads();

        // 2x-unrolled pixel-slice loop
        int j = slice;
        for (; j + NSLICE < m; j += 2 * NSLICE) {
            if (hv_inlier(fcx, fcy, sxy[j])) cnt++;
            if (hv_inlier(fcx, fcy, sxy[j + NSLICE])) cnt++;
        }
        if (j < m) {
            if (hv_inlier(fcx, fcy, sxy[j])) cnt++;
        }
        __syncthreads();
    }

    s_pcnt[slice][cl] = cnt;
    __syncthreads();

    if (slice == 0) {
        int tc = s_pcnt[0][cl] + s_pcnt[1][cl] + s_pcnt[2][cl] + s_pcnt[3][cl];
        skey[cl] = cv ? ((((unsigned)tc) << 13) | (unsigned)(8191 - c)) : 0u;
    }
    __syncthreads();

    for (int s = CBLK / 2; s > 0; s >>= 1) {
        if (tid < s) {
            unsigned o = skey[tid + s];
            if (o > skey[tid]) skey[tid] = o;
        }
        __syncthreads();
    }
    if (tid == 0)
        atomicMax(&g_bestkey[n][k], skey[0]);
}

// ================= K3: winner dsum + epilogue (1 block/n, warp per class) =================
__global__ void __launch_bounds__(320)
hv_final_kernel(const float* __restrict__ extents,
                const float* __restrict__ meta,
                float* __restrict__ out, int N)
{
    const int n    = blockIdx.x;
    const int warp = threadIdx.x >> 5;
    const int lane = threadIdx.x & 31;
    const unsigned FULL = 0xffffffffu;
    if (warp >= KD) return;

    const int k = warp + 1;
    unsigned bkey = g_bestkey[n][k];
    float votes = (float)(bkey >> 13);
    int   best  = 8191 - (int)(bkey & 8191u);
    int biy = best / GX, bix = best - biy * GX;
    float cx = (float)(bix * SKIP);
    float cy = (float)(biy * SKIP);

    const int beg = g_segStart[n][k];
    const int end = g_segStart[n][k + 1];

    float ds = 0.0f;
    for (int j = beg + lane; j < end; j += 32) {
        float4 t = g_sxyuv[n][j];
        if (hv_inlier(cx, cy, t)) ds += g_sd[n][j];
    }
    #pragma unroll
    for (int d = 16; d > 0; d >>= 1)
        ds += __shfl_down_sync(FULL, ds, d);

    if (lane == 0) {
        float davg = ds / fmaxf(votes, 1.0f);
        float cntk = g_counts[n][k];

        bool valid = (votes > 20.0f) && (votes > 0.1f * cntk)
                     && (cntk * (float)(SKIP * SKIP) > 500.0f);

        const float* mt = meta + (size_t)n * 9;
        float fx = mt[0], fy = mt[4], ppx = mt[2], ppy = mt[5];

        float e0 = extents[k * 3 + 0];
        float e1 = extents[k * 3 + 1];
        float e2 = extents[k * 3 + 2];
        float diam = sqrtf(e0 * e0 + e1 * e1 + e2 * e2) + EPSF;

        float hx = 0.5f * diam * fx / fmaxf(davg, EPSF);
        float hy = 0.5f * diam * fy / fmaxf(davg, EPSF);
        float score = valid ? votes : 0.0f;

        float* b = out + ((size_t)n * KD + (k - 1)) * 7;
        b[0] = (float)n;
        b[1] = (float)k;
        b[2] = cx - hx;
        b[3] = cy - hy;
        b[4] = cx + hx;
        b[5] = cy + hy;
        b[6] = score;

        float* ps = out + (size_t)N * KD * 7 + ((size_t)n * KD + (k - 1)) * 7;
        ps[0] = 1.0f; ps[1] = 0.0f; ps[2] = 0.0f; ps[3] = 0.0f;
        ps[4] = (cx - ppx) * davg / fx;
        ps[5] = (cy - ppy) * davg / fy;
        ps[6] = davg;

        out[(size_t)N * KD * 94 + (size_t)n * KD + (k - 1)] = (float)n;
    }
}

// ---------------- launch ----------------
extern "C" void kernel_launch(void* const* d_in, const int* in_sizes, int n_in,
                              void* d_out, int out_size)
{
    const int*   label   = (const int*)d_in[0];
    const float* vp      = (const float*)d_in[1];
    const float* extents = (const float*)d_in[2];
    const float* meta    = (const float*)d_in[4];
    float* out = (float*)d_out;

    int N = in_sizes[4] / 9;
    if (N < 1) N = 1;
    if (N > NMAX) N = NMAX;

    hv_prep_kernel<<<N, 1024>>>(label, vp, out, N);

    dim3 gv(VOTE_BX, KD, N);
    hv_vote_kernel<<<gv, VTHREADS>>>();

    hv_final_kernel<<<N, 320>>>(extents, meta, out, N);
}

// round 12
// speedup vs baseline: 1.2245x; 1.2245x over previous
#include <cuda_runtime.h>
#include <math.h>

#define NUM_CLASSES 10
#define Hh 480
#define Ww 640
#define SKIP 8
#define GY 60
#define GX 80
#define P  4800
#define NMAX 8
#define EPSF 1e-6f
#define INLIER 0.9f
#define RINL (1.0f / 0.9f)
#define GUARD 1.3e-5f
#define VTILE 512
#define CBLK  128                        // candidates per vote block (1 per thread-lane)
#define NSLICE 4
#define VTHREADS (CBLK * NSLICE)         // 512
#define VOTE_BX ((P + CBLK - 1) / CBLK)  // 38
#define KD (NUM_CLASSES - 1)

// ---------------- device scratch ----------------
static __device__ int      g_sidx[NMAX][P];       // sorted pos -> pixel index
static __device__ int      g_sklass[NMAX][P];     // sorted pos -> class
static __device__ float4   g_sxyuv[NMAX][P];      // sorted (x,y,u,v)
static __device__ float    g_sd[NMAX][P];         // sorted d
static __device__ int      g_segStart[NMAX][11];
static __device__ float    g_counts[NMAX][10];
static __device__ unsigned g_bestkey[NMAX][10];   // (cnt<<13)|(8191-c)

// Inlier predicate pieces. Fast scaled quadratic test; exact IEEE fallback in
// a guard band. Vote uses the warp-uniform ballot wrapper; final uses the
// per-lane wrapper — identical arithmetic, identical results.
__device__ __forceinline__ void hv_core(float fcx, float fcy, float4 t,
                                        float& s, float& dotv, float& gd)
{
    float dx = fcx - t.x;
    float dy = fcy - t.y;
    s    = fmaf(dx, dx, dy * dy);
    dotv = fmaf(t.z, dx, t.w * dy);
    float dp = fmaxf(dotv, 0.0f) * RINL;
    gd   = fmaf(dp, dp, -s);
}

__device__ __forceinline__ bool hv_exact(float s, float dotv)
{
    float rd = sqrtf(s) + EPSF;              // exact reference formula
    return (dotv / rd) > INLIER;
}

__device__ __forceinline__ bool hv_inlier(float fcx, float fcy, float4 t)
{
    float s, dotv, gd;
    hv_core(fcx, fcy, t, s, dotv, gd);
    bool inl = gd > 0.0f;
    if (fabsf(gd) < GUARD * s)
        inl = hv_exact(s, dotv);
    return inl;
}

// ================= K1: labels-only counting sort (1 block/n) =================
__global__ void __launch_bounds__(1024, 1)
hv_sort_kernel(const int* __restrict__ label)
{
    const int n    = blockIdx.x;
    const int tid  = threadIdx.x;
    const int warp = tid >> 5;
    const int lane = tid & 31;
    const unsigned FULL = 0xffffffffu;

    __shared__ int s_lab[P];
    __shared__ int s_cnt[32][10];
    __shared__ int s_off[32][10];

    if (tid < 10) g_bestkey[n][tid] = 0u;

    const int* lab2d = label + (size_t)n * Hh * Ww;
    for (int p = tid; p < P; p += 1024) {
        int iy = p / GX, ix = p - iy * GX;
        s_lab[p] = lab2d[iy * SKIP * Ww + ix * SKIP];
    }
    __syncthreads();

    // per-chunk per-class counts (warp = chunk of 150 pixels)
    int cnt[10];
    #pragma unroll
    for (int k = 0; k < 10; k++) cnt[k] = 0;
    const int cbase = warp * 150;
    #pragma unroll
    for (int s = 0; s < 5; s++) {
        int o = s * 32 + lane;
        int l = (o < 150) ? s_lab[cbase + o] : -1;
        #pragma unroll
        for (int k = 0; k < 10; k++) {
            unsigned m = __ballot_sync(FULL, l == k);
            cnt[k] += __popc(m);
        }
    }
    if (lane == 0) {
        #pragma unroll
        for (int k = 0; k < 10; k++) s_cnt[warp][k] = cnt[k];
    }
    __syncthreads();

    // warp 0: shfl-scan chunk offsets + segment starts
    if (warp == 0) {
        int segrun = 0;
        if (lane == 0) g_segStart[n][0] = 0;
        #pragma unroll
        for (int k = 0; k < 10; k++) {
            int v = s_cnt[lane][k];
            int incl = v;
            #pragma unroll
            for (int d = 1; d < 32; d <<= 1) {
                int t = __shfl_up_sync(FULL, incl, d);
                if (lane >= d) incl += t;
            }
            int excl  = incl - v;
            int total = __shfl_sync(FULL, incl, 31);
            if (k >= 1) {
                s_off[lane][k] = segrun + excl;
                if (lane == 0) g_segStart[n][k] = segrun;
                segrun += total;
            }
            if (lane == 0) g_counts[n][k] = (float)total;
        }
        if (lane == 0) g_segStart[n][10] = segrun;
    }
    __syncthreads();

    // parallel stable scatter of indices (warp = chunk)
    int off[10];
    #pragma unroll
    for (int k = 1; k < 10; k++) off[k] = s_off[warp][k];
    #pragma unroll
    for (int s = 0; s < 5; s++) {
        int o = s * 32 + lane;
        int j = cbase + o;
        int l = (o < 150) ? s_lab[j] : -1;
        #pragma unroll
        for (int k = 1; k < 10; k++) {
            unsigned m = __ballot_sync(FULL, l == k);
            if (l == k) {
                int pos = off[k] + __popc(m & ((1u << lane) - 1u));
                g_sidx[n][pos]   = j;
                g_sklass[n][pos] = k;
            }
            off[k] += __popc(m);
        }
    }
}

// ================= K2: parallel gather/compute + zero train outputs =================
__global__ void hv_gather_kernel(const float* __restrict__ vp,
                                 float* __restrict__ out, int N)
{
    const int n   = blockIdx.y;
    const int idx = blockIdx.x * blockDim.x + threadIdx.x;

    // zero train-only slices for this n
    if (idx < KD * 40) {
        out[(size_t)N * KD * 14 + (size_t)n * KD * 40 + idx] = 0.0f;
        out[(size_t)N * KD * 54 + (size_t)n * KD * 40 + idx] = 0.0f;
    }

    if (idx >= g_segStart[n][10]) return;

    int p = g_sidx[n][idx];
    int l = g_sklass[n][idx];
    int iy = p / GX, ix = p - iy * GX;

    const float* v3 = vp + (size_t)n * Hh * Ww * (3 * NUM_CLASSES)
                         + (size_t)(iy * SKIP * Ww + ix * SKIP) * (3 * NUM_CLASSES) + 3 * l;
    float u = v3[0], v = v3[1], w = v3[2];
    float nrm = sqrtf(u * u + v * v) + EPSF;

    g_sxyuv[n][idx] = make_float4((float)(ix * SKIP), (float)(iy * SKIP), u / nrm, v / nrm);
    g_sd[n][idx]    = expf(fminf(fmaxf(w, -3.0f), 3.0f));
}

// ================= K3: voting (counts only) + fused argmax, 512 thr =================
__global__ void __launch_bounds__(VTHREADS)
hv_vote_kernel()
{
    const int n = blockIdx.z;
    const int k = blockIdx.y + 1;
    const int tid   = threadIdx.x;
    const int cl    = tid & (CBLK - 1);          // candidate lane 0..127
    const int slice = tid >> 7;                  // 0..3
    const int c     = blockIdx.x * CBLK + cl;
    const unsigned FULL = 0xffffffffu;

    __shared__ float4   sxy[VTILE];
    __shared__ int      s_pcnt[NSLICE][CBLK];
    __shared__ unsigned skey[CBLK];

    const int beg = g_segStart[n][k];
    const int end = g_segStart[n][k + 1];

    float fcx = 0.f, fcy = 0.f;
    const bool cv = (c < P);
    if (cv) {
        int iy = c / GX, ix = c - iy * GX;
        fcx = (float)(ix * SKIP);
        fcy = (float)(iy * SKIP);
    }

    int cnt = 0;

    for (int base = beg; base < end; base += VTILE) {
        int m = end - base;
        if (m > VTILE) m = VTILE;
        for (int j = tid; j < m; j += VTHREADS)
            sxy[j] = g_sxyuv[n][base + j];
        __syncthreads();

        // 2x-unrolled pixel-slice loop; rare exact path hoisted behind a
        // warp-uniform ballot (all lanes of a warp share j).
        int j = slice;
        for (; j + NSLICE < m; j += 2 * NSLICE) {
            float4 t0 = sxy[j];
            float4 t1 = sxy[j + NSLICE];
            float s0, d0, g0, s1, d1, g1;
            hv_core(fcx, fcy, t0, s0, d0, g0);
            hv_core(fcx, fcy, t1, s1, d1, g1);
            bool i0 = g0 > 0.0f;
            bool i1 = g1 > 0.0f;
            bool sus0 = fabsf(g0) < GUARD * s0;
            bool sus1 = fabsf(g1) < GUARD * s1;
            if (__ballot_sync(FULL, sus0 || sus1)) {
                if (sus0) i0 = hv_exact(s0, d0);
                if (sus1) i1 = hv_exact(s1, d1);
            }
            cnt += (int)i0 + (int)i1;
        }
        if (j < m) {
            float4 t0 = sxy[j];
            float s0, d0, g0;
            hv_core(fcx, fcy, t0, s0, d0, g0);
            bool i0 = g0 > 0.0f;
            bool sus0 = fabsf(g0) < GUARD * s0;
            if (__ballot_sync(FULL, sus0)) {
                if (sus0) i0 = hv_exact(s0, d0);
            }
            cnt += (int)i0;
        }
        __syncthreads();
    }

    s_pcnt[slice][cl] = cnt;
    __syncthreads();

    if (slice == 0) {
        int tc = s_pcnt[0][cl] + s_pcnt[1][cl] + s_pcnt[2][cl] + s_pcnt[3][cl];
        skey[cl] = cv ? ((((unsigned)tc) << 13) | (unsigned)(8191 - c)) : 0u;
    }
    __syncthreads();

    for (int s = CBLK / 2; s > 0; s >>= 1) {
        if (tid < s) {
            unsigned o = skey[tid + s];
            if (o > skey[tid]) skey[tid] = o;
        }
        __syncthreads();
    }
    if (tid == 0)
        atomicMax(&g_bestkey[n][k], skey[0]);
}

// ================= K4: winner dsum + epilogue =================
__global__ void __launch_bounds__(256)
hv_final_kernel(const float* __restrict__ extents,
                const float* __restrict__ meta,
                float* __restrict__ out, int N)
{
    const int k   = blockIdx.x + 1;
    const int n   = blockIdx.y;
    const int tid = threadIdx.x;

    unsigned bkey = g_bestkey[n][k];
    float votes = (float)(bkey >> 13);
    int   best  = 8191 - (int)(bkey & 8191u);
    int biy = best / GX, bix = best - biy * GX;
    float cx = (float)(bix * SKIP);
    float cy = (float)(biy * SKIP);

    const int beg = g_segStart[n][k];
    const int end = g_segStart[n][k + 1];

    // recompute dsum at the winning candidate (identical predicate as vote)
    float ds = 0.0f;
    for (int j = beg + tid; j < end; j += 256) {
        float4 t = g_sxyuv[n][j];
        if (hv_inlier(cx, cy, t)) ds += g_sd[n][j];
    }
    __shared__ float rds[256];
    rds[tid] = ds;
    __syncthreads();
    for (int s = 128; s > 0; s >>= 1) {
        if (tid < s) rds[tid] += rds[tid + s];
        __syncthreads();
    }

    if (tid == 0) {
        float dsum = rds[0];
        float davg = dsum / fmaxf(votes, 1.0f);
        float cntk = g_counts[n][k];

        bool valid = (votes > 20.0f) && (votes > 0.1f * cntk)
                     && (cntk * (float)(SKIP * SKIP) > 500.0f);

        const float* mt = meta + (size_t)n * 9;
        float fx = mt[0], fy = mt[4], ppx = mt[2], ppy = mt[5];

        float e0 = extents[k * 3 + 0];
        float e1 = extents[k * 3 + 1];
        float e2 = extents[k * 3 + 2];
        float diam = sqrtf(e0 * e0 + e1 * e1 + e2 * e2) + EPSF;

        float hx = 0.5f * diam * fx / fmaxf(davg, EPSF);
        float hy = 0.5f * diam * fy / fmaxf(davg, EPSF);
        float score = valid ? votes : 0.0f;

        float* b = out + ((size_t)n * KD + (k - 1)) * 7;
        b[0] = (float)n;
        b[1] = (float)k;
        b[2] = cx - hx;
        b[3] = cy - hy;
        b[4] = cx + hx;
        b[5] = cy + hy;
        b[6] = score;

        float* ps = out + (size_t)N * KD * 7 + ((size_t)n * KD + (k - 1)) * 7;
        ps[0] = 1.0f; ps[1] = 0.0f; ps[2] = 0.0f; ps[3] = 0.0f;
        ps[4] = (cx - ppx) * davg / fx;
        ps[5] = (cy - ppy) * davg / fy;
        ps[6] = davg;

        out[(size_t)N * KD * 94 + (size_t)n * KD + (k - 1)] = (float)n;
    }
}

// ---------------- launch ----------------
extern "C" void kernel_launch(void* const* d_in, const int* in_sizes, int n_in,
                              void* d_out, int out_size)
{
    const int*   label   = (const int*)d_in[0];
    const float* vp      = (const float*)d_in[1];
    const float* extents = (const float*)d_in[2];
    const float* meta    = (const float*)d_in[4];
    float* out = (float*)d_out;

    int N = in_sizes[4] / 9;
    if (N < 1) N = 1;
    if (N > NMAX) N = NMAX;

    hv_sort_kernel<<<N, 1024>>>(label);

    dim3 gb((P + 255) / 256, N);
    hv_gather_kernel<<<gb, 256>>>(vp, out, N);

    dim3 gv(VOTE_BX, KD, N);
    hv_vote_kernel<<<gv, VTHREADS>>>();

    dim3 gf(KD, N);
    hv_final_kernel<<<gf, 256>>>(extents, meta, out, N);
}

// round 13
// speedup vs baseline: 1.2255x; 1.0009x over previous
#include <cuda_runtime.h>
#include <math.h>

#define NUM_CLASSES 10
#define Hh 480
#define Ww 640
#define SKIP 8
#define GY 60
#define GX 80
#define P  4800
#define NMAX 8
#define EPSF 1e-6f
#define INLIER 0.9f
#define RINL (1.0f / 0.9f)
#define GUARD 1.3e-5f
#define VTILE 512
#define CBLK  128                        // candidates per vote block (1 per thread-lane)
#define NSLICE 4
#define VTHREADS (CBLK * NSLICE)         // 512
#define VOTE_BX ((P + CBLK - 1) / CBLK)  // 38
#define KD (NUM_CLASSES - 1)

// ---------------- device scratch ----------------
static __device__ int      g_sidx[NMAX][P];       // sorted pos -> pixel index
static __device__ int      g_segStart[NMAX][11];
static __device__ float    g_counts[NMAX][10];
static __device__ unsigned g_bestkey[NMAX][10];   // (cnt<<13)|(8191-c)

// Inlier predicate pieces. Fast scaled quadratic test; exact IEEE fallback in
// a guard band. Vote uses the warp-uniform ballot wrapper; final uses the
// per-lane wrapper — identical arithmetic, identical results.
__device__ __forceinline__ void hv_core(float fcx, float fcy, float4 t,
                                        float& s, float& dotv, float& gd)
{
    float dx = fcx - t.x;
    float dy = fcy - t.y;
    s    = fmaf(dx, dx, dy * dy);
    dotv = fmaf(t.z, dx, t.w * dy);
    float dp = fmaxf(dotv, 0.0f) * RINL;
    gd   = fmaf(dp, dp, -s);
}

__device__ __forceinline__ bool hv_exact(float s, float dotv)
{
    float rd = sqrtf(s) + EPSF;              // exact reference formula
    return (dotv / rd) > INLIER;
}

__device__ __forceinline__ bool hv_inlier(float fcx, float fcy, float4 t)
{
    float s, dotv, gd;
    hv_core(fcx, fcy, t, s, dotv, gd);
    bool inl = gd > 0.0f;
    if (fabsf(gd) < GUARD * s)
        inl = hv_exact(s, dotv);
    return inl;
}

// gather one sorted pixel's (x,y,u,v) from vertex_pred — used identically by
// vote and final so values are bit-identical.
__device__ __forceinline__ float4 hv_gather_xyuv(const float* __restrict__ vp,
                                                 int n, int p, int k)
{
    int iy = p / GX, ix = p - iy * GX;
    const float* v3 = vp + (size_t)n * Hh * Ww * (3 * NUM_CLASSES)
                         + (size_t)(iy * SKIP * Ww + ix * SKIP) * (3 * NUM_CLASSES) + 3 * k;
    float u = v3[0], v = v3[1];
    float nrm = sqrtf(u * u + v * v) + EPSF;
    return make_float4((float)(ix * SKIP), (float)(iy * SKIP), u / nrm, v / nrm);
}

// ================= K1: labels-only counting sort (1 block/n) =================
__global__ void __launch_bounds__(1024, 1)
hv_sort_kernel(const int* __restrict__ label)
{
    const int n    = blockIdx.x;
    const int tid  = threadIdx.x;
    const int warp = tid >> 5;
    const int lane = tid & 31;
    const unsigned FULL = 0xffffffffu;

    __shared__ int s_lab[P];
    __shared__ int s_cnt[32][10];
    __shared__ int s_off[32][10];

    if (tid < 10) g_bestkey[n][tid] = 0u;

    const int* lab2d = label + (size_t)n * Hh * Ww;
    for (int p = tid; p < P; p += 1024) {
        int iy = p / GX, ix = p - iy * GX;
        s_lab[p] = lab2d[iy * SKIP * Ww + ix * SKIP];
    }
    __syncthreads();

    // per-chunk per-class counts (warp = chunk of 150 pixels)
    int cnt[10];
    #pragma unroll
    for (int k = 0; k < 10; k++) cnt[k] = 0;
    const int cbase = warp * 150;
    #pragma unroll
    for (int s = 0; s < 5; s++) {
        int o = s * 32 + lane;
        int l = (o < 150) ? s_lab[cbase + o] : -1;
        #pragma unroll
        for (int k = 0; k < 10; k++) {
            unsigned m = __ballot_sync(FULL, l == k);
            cnt[k] += __popc(m);
        }
    }
    if (lane == 0) {
        #pragma unroll
        for (int k = 0; k < 10; k++) s_cnt[warp][k] = cnt[k];
    }
    __syncthreads();

    // warp 0: shfl-scan chunk offsets + segment starts
    if (warp == 0) {
        int segrun = 0;
        if (lane == 0) g_segStart[n][0] = 0;
        #pragma unroll
        for (int k = 0; k < 10; k++) {
            int v = s_cnt[lane][k];
            int incl = v;
            #pragma unroll
            for (int d = 1; d < 32; d <<= 1) {
                int t = __shfl_up_sync(FULL, incl, d);
                if (lane >= d) incl += t;
            }
            int excl  = incl - v;
            int total = __shfl_sync(FULL, incl, 31);
            if (k >= 1) {
                s_off[lane][k] = segrun + excl;
                if (lane == 0) g_segStart[n][k] = segrun;
                segrun += total;
            }
            if (lane == 0) g_counts[n][k] = (float)total;
        }
        if (lane == 0) g_segStart[n][10] = segrun;
    }
    __syncthreads();

    // parallel stable scatter of indices (warp = chunk)
    int off[10];
    #pragma unroll
    for (int k = 1; k < 10; k++) off[k] = s_off[warp][k];
    #pragma unroll
    for (int s = 0; s < 5; s++) {
        int o = s * 32 + lane;
        int j = cbase + o;
        int l = (o < 150) ? s_lab[j] : -1;
        #pragma unroll
        for (int k = 1; k < 10; k++) {
            unsigned m = __ballot_sync(FULL, l == k);
            if (l == k) {
                int pos = off[k] + __popc(m & ((1u << lane) - 1u));
                g_sidx[n][pos] = j;
            }
            off[k] += __popc(m);
        }
    }
}

// ================= K2: voting (gathers from vp directly) + fused argmax =================
__global__ void __launch_bounds__(VTHREADS)
hv_vote_kernel(const float* __restrict__ vp)
{
    const int n = blockIdx.z;
    const int k = blockIdx.y + 1;
    const int tid   = threadIdx.x;
    const int cl    = tid & (CBLK - 1);          // candidate lane 0..127
    const int slice = tid >> 7;                  // 0..3
    const int c     = blockIdx.x * CBLK + cl;
    const unsigned FULL = 0xffffffffu;

    __shared__ float4   sxy[VTILE];
    __shared__ int      s_pcnt[NSLICE][CBLK];
    __shared__ unsigned skey[CBLK];

    const int beg = g_segStart[n][k];
    const int end = g_segStart[n][k + 1];

    float fcx = 0.f, fcy = 0.f;
    const bool cv = (c < P);
    if (cv) {
        int iy = c / GX, ix = c - iy * GX;
        fcx = (float)(ix * SKIP);
        fcy = (float)(iy * SKIP);
    }

    int cnt = 0;

    for (int base = beg; base < end; base += VTILE) {
        int m = end - base;
        if (m > VTILE) m = VTILE;
        // fused gather: sorted index -> (x,y,u,v) straight from vertex_pred
        for (int j = tid; j < m; j += VTHREADS) {
            int p = g_sidx[n][base + j];
            sxy[j] = hv_gather_xyuv(vp, n, p, k);
        }
        __syncthreads();

        // 2x-unrolled pixel-slice loop; rare exact path hoisted behind a
        // warp-uniform ballot (all lanes of a warp share j).
        int j = slice;
        for (; j + NSLICE < m; j += 2 * NSLICE) {
            float4 t0 = sxy[j];
            float4 t1 = sxy[j + NSLICE];
            float s0, d0, g0, s1, d1, g1;
            hv_core(fcx, fcy, t0, s0, d0, g0);
            hv_core(fcx, fcy, t1, s1, d1, g1);
            bool i0 = g0 > 0.0f;
            bool i1 = g1 > 0.0f;
            bool sus0 = fabsf(g0) < GUARD * s0;
            bool sus1 = fabsf(g1) < GUARD * s1;
            if (__ballot_sync(FULL, sus0 || sus1)) {
                if (sus0) i0 = hv_exact(s0, d0);
                if (sus1) i1 = hv_exact(s1, d1);
            }
            cnt += (int)i0 + (int)i1;
        }
        if (j < m) {
            float4 t0 = sxy[j];
            float s0, d0, g0;
            hv_core(fcx, fcy, t0, s0, d0, g0);
            bool i0 = g0 > 0.0f;
            bool sus0 = fabsf(g0) < GUARD * s0;
            if (__ballot_sync(FULL, sus0)) {
                if (sus0) i0 = hv_exact(s0, d0);
            }
            cnt += (int)i0;
        }
        __syncthreads();
    }

    s_pcnt[slice][cl] = cnt;
    __syncthreads();

    if (slice == 0) {
        int tc = s_pcnt[0][cl] + s_pcnt[1][cl] + s_pcnt[2][cl] + s_pcnt[3][cl];
        skey[cl] = cv ? ((((unsigned)tc) << 13) | (unsigned)(8191 - c)) : 0u;
    }
    __syncthreads();

    for (int s = CBLK / 2; s > 0; s >>= 1) {
        if (tid < s) {
            unsigned o = skey[tid + s];
            if (o > skey[tid]) skey[tid] = o;
        }
        __syncthreads();
    }
    if (tid == 0)
        atomicMax(&g_bestkey[n][k], skey[0]);
}

// ================= K3: winner dsum + epilogue + zero train outputs =================
__global__ void __launch_bounds__(256)
hv_final_kernel(const float* __restrict__ vp,
                const float* __restrict__ extents,
                const float* __restrict__ meta,
                float* __restrict__ out, int N)
{
    const int k   = blockIdx.x + 1;
    const int n   = blockIdx.y;
    const int tid = threadIdx.x;

    // zero train-only slices for this (n,k)
    if (tid < 40) {
        out[(size_t)N * KD * 14 + ((size_t)n * KD + (k - 1)) * 40 + tid] = 0.0f;
        out[(size_t)N * KD * 54 + ((size_t)n * KD + (k - 1)) * 40 + tid] = 0.0f;
    }

    unsigned bkey = g_bestkey[n][k];
    float votes = (float)(bkey >> 13);
    int   best  = 8191 - (int)(bkey & 8191u);
    int biy = best / GX, bix = best - biy * GX;
    float cx = (float)(bix * SKIP);
    float cy = (float)(biy * SKIP);

    const int beg = g_segStart[n][k];
    const int end = g_segStart[n][k + 1];

    // recompute dsum at the winning candidate (identical gather + predicate)
    float ds = 0.0f;
    for (int j = beg + tid; j < end; j += 256) {
        int p = g_sidx[n][j];
        float4 t = hv_gather_xyuv(vp, n, p, k);
        if (hv_inlier(cx, cy, t)) {
            int iy = p / GX, ix = p - iy * GX;
            float w = vp[(size_t)n * Hh * Ww * (3 * NUM_CLASSES)
                         + (size_t)(iy * SKIP * Ww + ix * SKIP) * (3 * NUM_CLASSES) + 3 * k + 2];
            ds += expf(fminf(fmaxf(w, -3.0f), 3.0f));
        }
    }
    __shared__ float rds[256];
    rds[tid] = ds;
    __syncthreads();
    for (int s = 128; s > 0; s >>= 1) {
        if (tid < s) rds[tid] += rds[tid + s];
        __syncthreads();
    }

    if (tid == 0) {
        float dsum = rds[0];
        float davg = dsum / fmaxf(votes, 1.0f);
        float cntk = g_counts[n][k];

        bool valid = (votes > 20.0f) && (votes > 0.1f * cntk)
                     && (cntk * (float)(SKIP * SKIP) > 500.0f);

        const float* mt = meta + (size_t)n * 9;
        float fx = mt[0], fy = mt[4], ppx = mt[2], ppy = mt[5];

        float e0 = extents[k * 3 + 0];
        float e1 = extents[k * 3 + 1];
        float e2 = extents[k * 3 + 2];
        float diam = sqrtf(e0 * e0 + e1 * e1 + e2 * e2) + EPSF;

        float hx = 0.5f * diam * fx / fmaxf(davg, EPSF);
        float hy = 0.5f * diam * fy / fmaxf(davg, EPSF);
        float score = valid ? votes : 0.0f;

        float* b = out + ((size_t)n * KD + (k - 1)) * 7;
        b[0] = (float)n;
        b[1] = (float)k;
        b[2] = cx - hx;
        b[3] = cy - hy;
        b[4] = cx + hx;
        b[5] = cy + hy;
        b[6] = score;

        float* ps = out + (size_t)N * KD * 7 + ((size_t)n * KD + (k - 1)) * 7;
        ps[0] = 1.0f; ps[1] = 0.0f; ps[2] = 0.0f; ps[3] = 0.0f;
        ps[4] = (cx - ppx) * davg / fx;
        ps[5] = (cy - ppy) * davg / fy;
        ps[6] = davg;

        out[(size_t)N * KD * 94 + (size_t)n * KD + (k - 1)] = (float)n;
    }
}

// ---------------- launch ----------------
extern "C" void kernel_launch(void* const* d_in, const int* in_sizes, int n_in,
                              void* d_out, int out_size)
{
    const int*   label   = (const int*)d_in[0];
    const float* vp      = (const float*)d_in[1];
    const float* extents = (const float*)d_in[2];
    const float* meta    = (const float*)d_in[4];
    float* out = (float*)d_out;

    int N = in_sizes[4] / 9;
    if (N < 1) N = 1;
    if (N > NMAX) N = NMAX;

    hv_sort_kernel<<<N, 1024>>>(label);

    dim3 gv(VOTE_BX, KD, N);
    hv_vote_kernel<<<gv, VTHREADS>>>(vp);

    dim3 gf(KD, N);
    hv_final_kernel<<<gf, 256>>>(vp, extents, meta, out, N);
}